// round 3
// baseline (speedup 1.0000x reference)
#include <cuda_runtime.h>

#define MAXN 512

// ---- device scratch (no allocations allowed) ----
__device__ float g_A[MAXN * MAXN];
__device__ float g_rad[MAXN];
__device__ float g_ang[MAXN];

__device__ __forceinline__ float warp_sum(float v) {
    v += __shfl_down_sync(0xffffffffu, v, 16);
    v += __shfl_down_sync(0xffffffffu, v, 8);
    v += __shfl_down_sync(0xffffffffu, v, 4);
    v += __shfl_down_sync(0xffffffffu, v, 2);
    v += __shfl_down_sync(0xffffffffu, v, 1);
    return v;
}

// K1: pairwise A matrix + radial descriptor. One CTA per atom i.
__global__ void pair_kernel(const float* __restrict__ x, int N) {
    const int i = blockIdx.x;
    const float xi0 = x[3 * i], xi1 = x[3 * i + 1], xi2 = x[3 * i + 2];
    float rad = 0.f;
    float* Arow = g_A + i * N;
    for (int j = threadIdx.x; j < N; j += blockDim.x) {
        float dx = xi0 - x[3 * j];
        float dy = xi1 - x[3 * j + 1];
        float dz = xi2 - x[3 * j + 2];
        float D2 = fmaf(dx, dx, fmaf(dy, dy, dz * dz));
        float a = 0.f;
        if (j != i && D2 <= 36.f) {
            float inv = rsqrtf(D2);
            float D = D2 * inv;
            float fc = 0.5f * (__cosf(0.5235987755982988f * D) + 1.f);
            a = __expf(-0.5f * D2) * fc;           // ETA = 0.5
            float dm = D - 1.f;                    // RS = 1
            rad += __expf(-0.5f * dm * dm) * fc;
        }
        Arow[j] = a;
    }
    __shared__ float wr[4];
    rad = warp_sum(rad);
    if ((threadIdx.x & 31) == 0) wr[threadIdx.x >> 5] = rad;
    __syncthreads();
    if (threadIdx.x == 0) g_rad[i] = wr[0] + wr[1] + wr[2] + wr[3];
}

// K2: angular triplet sum with neighbor compaction. One CTA per atom i.
__global__ __launch_bounds__(256) void tri_kernel(const float* __restrict__ x, int N) {
    const int i = blockIdx.x;
    __shared__ float4 u4[MAXN];   // {ux, uy, uz, a_ij} unit vectors (x_i - x_j)/D
    __shared__ int   jidx[MAXN];  // original neighbor index
    __shared__ int   Msh;
    __shared__ float wr[8];
    const int tid = threadIdx.x;

    // deterministic warp-0 stream compaction of neighbors of i
    if (tid < 32) {
        const float xi0 = x[3 * i], xi1 = x[3 * i + 1], xi2 = x[3 * i + 2];
        int base = 0;
        for (int j0 = 0; j0 < N; j0 += 32) {
            int j = j0 + tid;
            float dx = 0.f, dy = 0.f, dz = 0.f, D2 = 1e9f;
            if (j < N) {
                dx = xi0 - x[3 * j];
                dy = xi1 - x[3 * j + 1];
                dz = xi2 - x[3 * j + 2];
                D2 = fmaf(dx, dx, fmaf(dy, dy, dz * dz));
            }
            bool valid = (j < N) && (j != i) && (D2 <= 36.f);
            unsigned mask = __ballot_sync(0xffffffffu, valid);
            if (valid) {
                float inv = rsqrtf(D2);
                float D = D2 * inv;
                float fc = 0.5f * (__cosf(0.5235987755982988f * D) + 1.f);
                float a = __expf(-0.5f * D2) * fc;
                int pos = base + __popc(mask & ((1u << tid) - 1u));
                u4[pos] = make_float4(dx * inv, dy * inv, dz * inv, a);
                jidx[pos] = j;
            }
            base += __popc(mask);
        }
        if (tid == 0) Msh = base;
    }
    __syncthreads();

    const int M = Msh;
    const int ty = tid >> 4;
    const int tx = tid & 15;
    float acc = 0.f;

    for (int jj0 = 0; jj0 < M; jj0 += 16) {
        const int jj = jj0 + ty;
        const bool jval = (jj < M);
        float4 vj = jval ? u4[jj] : make_float4(0.f, 0.f, 0.f, 0.f);
        const float* rowj = g_A + (jval ? jidx[jj] : 0) * N;
        // fold lambda=0.8 and the (1 - lambda*dot) sign into the j-vector
        const float nvx = -0.8f * vj.x;
        const float nvy = -0.8f * vj.y;
        const float nvz = -0.8f * vj.z;
        const float wj  = vj.w;  // a_ij

        for (int kk0 = jj0; kk0 < M; kk0 += 16) {
            const int kk = kk0 + tx;
            const bool kval = jval && (kk > jj) && (kk < M);
            if (kval) {
                float4 uk = u4[kk];
                float ajk = __ldg(rowj + jidx[kk]);
                // t = 1 + lambda*cos(theta) = 1 - lambda * (u_ij . u_ik)
                float t = fmaf(nvx, uk.x, fmaf(nvy, uk.y, fmaf(nvz, uk.z, 1.0f)));
                t = fmaxf(t, 1e-6f);
                float p = __expf(0.6f * __logf(t));     // t^ZETA via MUFU LG2/EX2
                acc = fmaf(p, wj * (uk.w * ajk), acc);  // p * a_ij * a_ik * a_jk
            }
        }
    }

    acc = warp_sum(acc);
    if ((tid & 31) == 0) wr[tid >> 5] = acc;
    __syncthreads();
    if (tid == 0) {
        float s = 0.f;
        #pragma unroll
        for (int w = 0; w < 8; w++) s += wr[w];
        g_ang[i] = 1.3195079107728942f * s;  // 2^(1-ZETA), ZETA=0.6
    }
}

// K3: two tiny MLPs (2->40->40->1), one thread per atom; atom 8 -> net b.
__global__ __launch_bounds__(128) void mlp_kernel(
    const float* __restrict__ w1a, const float* __restrict__ b1a,
    const float* __restrict__ w2a, const float* __restrict__ b2a,
    const float* __restrict__ w3a, const float* __restrict__ b3a,
    const float* __restrict__ w1b, const float* __restrict__ b1b,
    const float* __restrict__ w2b, const float* __restrict__ b2b,
    const float* __restrict__ w3b, const float* __restrict__ b3b,
    float* __restrict__ out, int N)
{
    // per-net layout: w1[80] | b1[40] @80 | w2[1600] @120 | b2[40] @1720 | w3[40] @1760 | b3 @1800
    __shared__ float s[2 * 1801];
    const int tid = threadIdx.x;
    for (int t = tid; t < 80; t += blockDim.x)   { s[t] = w1a[t];            s[1801 + t] = w1b[t]; }
    for (int t = tid; t < 40; t += blockDim.x) {
        s[80 + t]   = b1a[t];  s[1801 + 80 + t]   = b1b[t];
        s[1720 + t] = b2a[t];  s[1801 + 1720 + t] = b2b[t];
        s[1760 + t] = w3a[t];  s[1801 + 1760 + t] = w3b[t];
    }
    for (int t = tid; t < 1600; t += blockDim.x) { s[120 + t] = w2a[t];      s[1801 + 120 + t] = w2b[t]; }
    if (tid == 0) { s[1800] = b3a[0]; s[1801 + 1800] = b3b[0]; }
    __syncthreads();

    const int i = blockIdx.x * blockDim.x + tid;
    if (i >= N) return;
    const float* W = s + ((i == 8) ? 1801 : 0);   // SPECIAL_ATOM = 8
    const float g0 = g_ang[i];
    const float g1 = g_rad[i];

    float h1[40];
    #pragma unroll
    for (int o = 0; o < 40; o++) {
        float z = fmaf(W[2 * o], g0, fmaf(W[2 * o + 1], g1, W[80 + o]));
        h1[o] = __fdividef(1.f, fmaf(z, z, 1.f));  // 1/(1+z^2)
    }
    float h2[40];
    #pragma unroll
    for (int o = 0; o < 40; o++) {
        float z = W[1720 + o];
        #pragma unroll 8
        for (int k = 0; k < 40; k++) z = fmaf(W[120 + o * 40 + k], h1[k], z);
        h2[o] = __fdividef(1.f, fmaf(z, z, 1.f));
    }
    float z = W[1800];
    #pragma unroll 8
    for (int k = 0; k < 40; k++) z = fmaf(W[1760 + k], h2[k], z);
    out[i] = z;
}

extern "C" void kernel_launch(void* const* d_in, const int* in_sizes, int n_in,
                              void* d_out, int out_size) {
    const float* x = (const float*)d_in[0];
    const int N = in_sizes[0] / 3;

    pair_kernel<<<N, 128>>>(x, N);
    tri_kernel<<<N, 256>>>(x, N);

    const int grid = (N + 127) / 128;
    mlp_kernel<<<grid, 128>>>(
        (const float*)d_in[1],  (const float*)d_in[2],  (const float*)d_in[3],
        (const float*)d_in[4],  (const float*)d_in[5],  (const float*)d_in[6],
        (const float*)d_in[7],  (const float*)d_in[8],  (const float*)d_in[9],
        (const float*)d_in[10], (const float*)d_in[11], (const float*)d_in[12],
        (float*)d_out, N);
}

// round 4
// speedup vs baseline: 1.0908x; 1.0908x over previous
#include <cuda_runtime.h>

#define MAXN 512

// ---- device scratch (no allocations allowed) ----
__device__ float g_rad[MAXN];
__device__ float g_angp[2][MAXN];   // per-half partial angular sums (deterministic combine in mlp)

__device__ __forceinline__ float warp_sum(float v) {
    v += __shfl_down_sync(0xffffffffu, v, 16);
    v += __shfl_down_sync(0xffffffffu, v, 8);
    v += __shfl_down_sync(0xffffffffu, v, 4);
    v += __shfl_down_sync(0xffffffffu, v, 2);
    v += __shfl_down_sync(0xffffffffu, v, 1);
    return v;
}

__device__ __forceinline__ float fast_lg2(float x) {
    float r; asm("lg2.approx.ftz.f32 %0, %1;" : "=f"(r) : "f"(x)); return r;
}
__device__ __forceinline__ float fast_ex2(float x) {
    float r; asm("ex2.approx.ftz.f32 %0, %1;" : "=f"(r) : "f"(x)); return r;
}

// K1: angular (triplet) + radial descriptors. TWO CTAs per atom (jj-parity split).
// No A matrix: a_jk is recomputed per triplet from the law of cosines, using the
// same dot product needed for cos(theta).
__global__ __launch_bounds__(256) void tri_kernel(const float* __restrict__ x, int N) {
    const int i    = blockIdx.x >> 1;
    const int half = blockIdx.x & 1;
    __shared__ float4 u4[MAXN];   // {ux, uy, uz, D}  unit vector of (x_i - x_j), distance
    __shared__ float2 db[MAXN];   // {D^2, a_ij}
    __shared__ int   Msh;
    __shared__ float wr[8];
    const int tid  = threadIdx.x;
    const int lane = tid & 31;
    const int w    = tid >> 5;

    // deterministic warp-0 stream compaction of neighbors of i (+ radial descriptor)
    if (w == 0) {
        const float xi0 = x[3 * i], xi1 = x[3 * i + 1], xi2 = x[3 * i + 2];
        int base = 0;
        float rad = 0.f;
        for (int j0 = 0; j0 < N; j0 += 32) {
            int j = j0 + lane;
            float dx = 0.f, dy = 0.f, dz = 0.f, D2 = 1e9f;
            if (j < N) {
                dx = xi0 - x[3 * j];
                dy = xi1 - x[3 * j + 1];
                dz = xi2 - x[3 * j + 2];
                D2 = fmaf(dx, dx, fmaf(dy, dy, dz * dz));
            }
            bool valid = (j < N) && (j != i) && (D2 <= 36.f);
            unsigned mask = __ballot_sync(0xffffffffu, valid);
            if (valid) {
                float inv = rsqrtf(D2);
                float D = D2 * inv;
                float fc = fmaf(0.5f, __cosf(0.5235987755982988f * D), 0.5f);
                float a = __expf(-0.5f * D2) * fc;          // ETA = 0.5
                float dm = D - 1.f;                          // RS = 1
                rad += __expf(-0.5f * dm * dm) * fc;
                int pos = base + __popc(mask & ((1u << lane) - 1u));
                u4[pos] = make_float4(dx * inv, dy * inv, dz * inv, D);
                db[pos] = make_float2(D2, a);
            }
            base += __popc(mask);
        }
        rad = warp_sum(rad);
        if (lane == 0) {
            Msh = base;
            if (half == 0) g_rad[i] = rad;
        }
    }
    __syncthreads();

    const int M = Msh;
    float acc = 0.f;

    // each warp takes jj rows of its parity class, interleaved for balance
    for (int jj = 8 * half + w; jj < M; jj += 16) {
        const float4 uj  = u4[jj];
        const float2 bj  = db[jj];
        const float Dj   = uj.w;
        const float Dj2  = bj.x;
        const float aij  = bj.y;
        const float cneg = -2.f * Dj;          // for D_jk^2 = Dj^2 + Dk^2 - 2 Dj Dk dot

        for (int kk0 = (jj + 1) & ~31; kk0 < M; kk0 += 32) {
            const int kk = kk0 + lane;
            const bool val = (kk > jj) && (kk < M);
            const int kc = val ? kk : 0;
            const float4 uk = u4[kc];
            const float2 bk = db[kc];

            // dot = u_ij . u_ik  (cos_theta in ref is -dot since Rij = -d_j)
            float dot = fmaf(uj.x, uk.x, fmaf(uj.y, uk.y, uj.z * uk.z));
            float t = fmaf(-0.8f, dot, 1.0f);          // 1 + LAMDA*cos_theta
            t = fmaxf(t, 1e-6f);

            float qk   = cneg * uk.w;                   // -2 Dj Dk
            float sk   = Dj2 + bk.x;                    // Dj^2 + Dk^2
            float Djk2 = fmaf(qk, dot, sk);
            Djk2 = fmaxf(Djk2, 1e-12f);                 // guard cancellation

            // fused t^0.6 * exp(-0.5*Djk2)  ->  single EX2
            float z = fmaf(0.6f, fast_lg2(t), -0.72134752044448f * Djk2);
            float P = fast_ex2(z);

            float invd = rsqrtf(Djk2);
            float Djk  = Djk2 * invd;
            float fc   = fmaf(0.5f, __cosf(0.5235987755982988f * Djk), 0.5f);

            if (val && Djk2 <= 36.f)
                acc = fmaf(P * fc, aij * bk.y, acc);    // * a_ij * a_ik * a_jk
        }
    }

    acc = warp_sum(acc);
    if (lane == 0) wr[w] = acc;
    __syncthreads();
    if (tid == 0) {
        float s = 0.f;
        #pragma unroll
        for (int q = 0; q < 8; q++) s += wr[q];
        g_angp[half][i] = s;
    }
}

// K2: two tiny MLPs (2->40->40->1). One 64-thread CTA per atom; atom 8 -> net b.
__global__ __launch_bounds__(64) void mlp_kernel(
    const float* __restrict__ w1a, const float* __restrict__ b1a,
    const float* __restrict__ w2a, const float* __restrict__ b2a,
    const float* __restrict__ w3a, const float* __restrict__ b3a,
    const float* __restrict__ w1b, const float* __restrict__ b1b,
    const float* __restrict__ w2b, const float* __restrict__ b2b,
    const float* __restrict__ w3b, const float* __restrict__ b3b,
    float* __restrict__ out, int N)
{
    const int i = blockIdx.x;
    const int t = threadIdx.x;
    const bool sp = (i == 8);   // SPECIAL_ATOM
    const float* W1 = sp ? w1b : w1a;  const float* B1 = sp ? b1b : b1a;
    const float* W2 = sp ? w2b : w2a;  const float* B2 = sp ? b2b : b2a;
    const float* W3 = sp ? w3b : w3a;  const float* B3 = sp ? b3b : b3a;

    __shared__ float h1[40], h2[40];

    const float g0 = 1.3195079107728942f * (g_angp[0][i] + g_angp[1][i]);  // 2^(1-ZETA)
    const float g1 = g_rad[i];

    if (t < 40) {
        float z = fmaf(W1[2 * t], g0, fmaf(W1[2 * t + 1], g1, B1[t]));
        h1[t] = __fdividef(1.f, fmaf(z, z, 1.f));
    }
    __syncthreads();
    if (t < 40) {
        float z = B2[t];
        const float* row = W2 + t * 40;
        #pragma unroll 8
        for (int k = 0; k < 40; k++) z = fmaf(row[k], h1[k], z);
        h2[t] = __fdividef(1.f, fmaf(z, z, 1.f));
    }
    __syncthreads();
    if (t == 0) {
        float z = B3[0];
        #pragma unroll 8
        for (int k = 0; k < 40; k++) z = fmaf(W3[k], h2[k], z);
        out[i] = z;
    }
}

extern "C" void kernel_launch(void* const* d_in, const int* in_sizes, int n_in,
                              void* d_out, int out_size) {
    const float* x = (const float*)d_in[0];
    const int N = in_sizes[0] / 3;

    tri_kernel<<<2 * N, 256>>>(x, N);

    mlp_kernel<<<N, 64>>>(
        (const float*)d_in[1],  (const float*)d_in[2],  (const float*)d_in[3],
        (const float*)d_in[4],  (const float*)d_in[5],  (const float*)d_in[6],
        (const float*)d_in[7],  (const float*)d_in[8],  (const float*)d_in[9],
        (const float*)d_in[10], (const float*)d_in[11], (const float*)d_in[12],
        (float*)d_out, N);
}

// round 5
// speedup vs baseline: 1.3646x; 1.2510x over previous
#include <cuda_runtime.h>

#define MAXN 512

// ---- device scratch (no allocations allowed) ----
__device__ float g_rad[MAXN];
__device__ float g_ang[MAXN];

__device__ __forceinline__ float warp_sum(float v) {
    v += __shfl_down_sync(0xffffffffu, v, 16);
    v += __shfl_down_sync(0xffffffffu, v, 8);
    v += __shfl_down_sync(0xffffffffu, v, 4);
    v += __shfl_down_sync(0xffffffffu, v, 2);
    v += __shfl_down_sync(0xffffffffu, v, 1);
    return v;
}

__device__ __forceinline__ float fast_lg2(float x) {
    float r; asm("lg2.approx.ftz.f32 %0, %1;" : "=f"(r) : "f"(x)); return r;
}
__device__ __forceinline__ float fast_ex2(float x) {
    float r; asm("ex2.approx.ftz.f32 %0, %1;" : "=f"(r) : "f"(x)); return r;
}

// K1: angular + radial descriptors. ONE 512-thread CTA per atom.
// Cooperative 12-warp compaction, padded neighbor list, a_jk recomputed via
// law of cosines from the same dot product used for cos(theta).
__global__ __launch_bounds__(512, 2) void tri_kernel(const float* __restrict__ x, int N) {
    const int i = blockIdx.x;
    __shared__ float4 u4[MAXN];   // {ux, uy, uz, D}
    __shared__ float2 db[MAXN];   // {D^2, a_ij}
    __shared__ int   cnt[16];
    __shared__ int   off[16];
    __shared__ float red[16];
    __shared__ float wr[16];
    __shared__ int   Msh;
    const int tid  = threadIdx.x;
    const int lane = tid & 31;
    const int w    = tid >> 5;

    const float xi0 = x[3 * i], xi1 = x[3 * i + 1], xi2 = x[3 * i + 2];

    // --- phase 1: each of warps 0..11 handles one 32-atom chunk ---
    float dx = 0.f, dy = 0.f, dz = 0.f, D2 = 1e9f, D = 0.f, inv = 0.f, a = 0.f;
    bool valid = false;
    int rank = 0;
    const int nchunk = (N + 31) >> 5;   // 12 for N=384
    if (w < nchunk) {
        int j = w * 32 + lane;
        float radp = 0.f;
        if (j < N) {
            dx = xi0 - x[3 * j];
            dy = xi1 - x[3 * j + 1];
            dz = xi2 - x[3 * j + 2];
            D2 = fmaf(dx, dx, fmaf(dy, dy, dz * dz));
            valid = (j != i) && (D2 <= 36.f);
        }
        unsigned mask = __ballot_sync(0xffffffffu, valid);
        if (valid) {
            inv = rsqrtf(D2);
            D = D2 * inv;
            float fc = fmaf(0.5f, __cosf(0.5235987755982988f * D), 0.5f);
            a = __expf(-0.5f * D2) * fc;          // ETA = 0.5
            float dm = D - 1.f;                    // RS = 1
            radp = __expf(-0.5f * dm * dm) * fc;
            rank = __popc(mask & ((1u << lane) - 1u));
        }
        radp = warp_sum(radp);
        if (lane == 0) { cnt[w] = __popc(mask); red[w] = radp; }
    } else if (lane == 0) {
        cnt[w] = 0; red[w] = 0.f;
    }
    __syncthreads();

    // --- phase 2: warp 0 lanes 0..15: prefix scan of counts + radial total ---
    if (tid < 16) {
        int c = cnt[tid];
        int cs = c;
        #pragma unroll
        for (int d = 1; d < 16; d <<= 1) {
            int t = __shfl_up_sync(0xffffu, cs, d);
            if (tid >= d) cs += t;
        }
        off[tid] = cs - c;          // exclusive prefix
        if (tid == 15) Msh = cs;
        float r = red[tid];
        #pragma unroll
        for (int d = 8; d >= 1; d >>= 1) r += __shfl_down_sync(0xffffu, r, d);
        if (tid == 0) g_rad[i] = r;
    }
    __syncthreads();

    // --- phase 3: scatter compacted entries ---
    if (valid) {
        int pos = off[w] + rank;
        u4[pos] = make_float4(dx * inv, dy * inv, dz * inv, D);
        db[pos] = make_float2(D2, a);
    }
    __syncthreads();

    const int M = Msh;
    const int Mpad = (M + 31) & ~31;
    // --- phase 4: pad with far-away sentinels (predicated off via Djk2 > 36) ---
    if (tid < Mpad - M) {
        int p = M + tid;
        u4[p] = make_float4(0.f, 0.f, 0.f, 1e3f);
        db[p] = make_float2(1e6f, 0.f);
    }
    __syncthreads();

    // --- phase 5: triplet loop. warp w owns rows jj = w, w+16, ... ---
    float accw = 0.f;
    for (int jj = w; jj < M; jj += 16) {
        const float4 uj = u4[jj];
        const float2 bj = db[jj];
        const float cneg = -2.f * uj.w;
        float accr = 0.f;

        for (int kk0 = (jj + 1) & ~31; kk0 < Mpad; kk0 += 32) {
            const int kk = kk0 + lane;
            const float4 uk = u4[kk];
            const float2 bk = db[kk];

            float dot = fmaf(uj.x, uk.x, fmaf(uj.y, uk.y, uj.z * uk.z));
            float t = fmaxf(fmaf(-0.8f, dot, 1.0f), 1e-6f);          // 1 + LAMDA*cos
            float Djk2 = fmaf(cneg * uk.w, dot, bj.x + bk.x);
            float Djk2m = fmaxf(Djk2, 1e-12f);

            // fused t^0.6 * exp(-0.5*Djk2) -> one EX2
            float z = fmaf(0.6f, fast_lg2(t), -0.72134752044448f * Djk2m);
            float P = fast_ex2(z);

            float invd = rsqrtf(Djk2m);
            float Djk  = Djk2m * invd;
            float fc = fmaf(0.5f, __cosf(0.5235987755982988f * Djk), 0.5f);

            if (kk > jj && Djk2 <= 36.f)
                accr = fmaf(P * fc, bk.y, accr);   // * a_ik * a_jk (a_ij hoisted)
        }
        accw = fmaf(bj.y, accr, accw);
    }

    accw = warp_sum(accw);
    if (lane == 0) wr[w] = accw;
    __syncthreads();
    if (tid < 16) {
        float s = wr[tid];
        #pragma unroll
        for (int d = 8; d >= 1; d >>= 1) s += __shfl_down_sync(0xffffu, s, d);
        if (tid == 0) g_ang[i] = 1.3195079107728942f * s;   // 2^(1-ZETA)
    }
}

// K2: two tiny MLPs (2->40->40->1). Thread-per-atom, weights staged in smem.
// Launched twice with 192 atoms each.
__global__ __launch_bounds__(192) void mlp_kernel(
    const float* __restrict__ w1a, const float* __restrict__ b1a,
    const float* __restrict__ w2a, const float* __restrict__ b2a,
    const float* __restrict__ w3a, const float* __restrict__ b3a,
    const float* __restrict__ w1b, const float* __restrict__ b1b,
    const float* __restrict__ w2b, const float* __restrict__ b2b,
    const float* __restrict__ w3b, const float* __restrict__ b3b,
    float* __restrict__ out, int base, int N)
{
    // per-net layout: w1[80] | b1[40] @80 | w2[1600] @120 | b2[40] @1720 | w3[40] @1760 | b3 @1800
    __shared__ float s[2 * 1802];
    const int tid = threadIdx.x;
    for (int t = tid; t < 80; t += blockDim.x)   { s[t] = w1a[t];            s[1802 + t] = w1b[t]; }
    for (int t = tid; t < 40; t += blockDim.x) {
        s[80 + t]   = b1a[t];  s[1802 + 80 + t]   = b1b[t];
        s[1720 + t] = b2a[t];  s[1802 + 1720 + t] = b2b[t];
        s[1760 + t] = w3a[t];  s[1802 + 1760 + t] = w3b[t];
    }
    for (int t = tid; t < 1600; t += blockDim.x) { s[120 + t] = w2a[t];      s[1802 + 120 + t] = w2b[t]; }
    if (tid == 0) { s[1800] = b3a[0]; s[1802 + 1800] = b3b[0]; }
    __syncthreads();

    const int i = base + tid;
    if (i >= N) return;
    const float* W = s + ((i == 8) ? 1802 : 0);   // SPECIAL_ATOM = 8
    const float g0 = g_ang[i];
    const float g1 = g_rad[i];

    float h1[40];
    #pragma unroll
    for (int o = 0; o < 40; o++) {
        float z = fmaf(W[2 * o], g0, fmaf(W[2 * o + 1], g1, W[80 + o]));
        h1[o] = __fdividef(1.f, fmaf(z, z, 1.f));  // 1/(1+z^2)
    }
    float h2[40];
    #pragma unroll
    for (int o = 0; o < 40; o++) {
        float z = W[1720 + o];
        const float2* row = (const float2*)(W + 120 + o * 40);
        #pragma unroll
        for (int k = 0; k < 20; k++) {
            float2 ww = row[k];
            z = fmaf(ww.x, h1[2 * k], z);
            z = fmaf(ww.y, h1[2 * k + 1], z);
        }
        h2[o] = __fdividef(1.f, fmaf(z, z, 1.f));
    }
    float z = W[1800];
    #pragma unroll 8
    for (int k = 0; k < 40; k++) z = fmaf(W[1760 + k], h2[k], z);
    out[i] = z;
}

extern "C" void kernel_launch(void* const* d_in, const int* in_sizes, int n_in,
                              void* d_out, int out_size) {
    const float* x = (const float*)d_in[0];
    const int N = in_sizes[0] / 3;

    tri_kernel<<<N, 512>>>(x, N);

    const int halfA = (N + 1) / 2;
    mlp_kernel<<<1, 192>>>(
        (const float*)d_in[1],  (const float*)d_in[2],  (const float*)d_in[3],
        (const float*)d_in[4],  (const float*)d_in[5],  (const float*)d_in[6],
        (const float*)d_in[7],  (const float*)d_in[8],  (const float*)d_in[9],
        (const float*)d_in[10], (const float*)d_in[11], (const float*)d_in[12],
        (float*)d_out, 0, halfA < N ? halfA : N);
    mlp_kernel<<<1, 192>>>(
        (const float*)d_in[1],  (const float*)d_in[2],  (const float*)d_in[3],
        (const float*)d_in[4],  (const float*)d_in[5],  (const float*)d_in[6],
        (const float*)d_in[7],  (const float*)d_in[8],  (const float*)d_in[9],
        (const float*)d_in[10], (const float*)d_in[11], (const float*)d_in[12],
        (float*)d_out, halfA, N);
}

// round 6
// speedup vs baseline: 1.4081x; 1.0319x over previous
#include <cuda_runtime.h>

#define MAXN 512
#define SPECIAL_ATOM 8

__device__ __forceinline__ float warp_sum(float v) {
    v += __shfl_down_sync(0xffffffffu, v, 16);
    v += __shfl_down_sync(0xffffffffu, v, 8);
    v += __shfl_down_sync(0xffffffffu, v, 4);
    v += __shfl_down_sync(0xffffffffu, v, 2);
    v += __shfl_down_sync(0xffffffffu, v, 1);
    return v;
}

__device__ __forceinline__ float fast_lg2(float x) {
    float r; asm("lg2.approx.ftz.f32 %0, %1;" : "=f"(r) : "f"(x)); return r;
}
__device__ __forceinline__ float fast_ex2(float x) {
    float r; asm("ex2.approx.ftz.f32 %0, %1;" : "=f"(r) : "f"(x)); return r;
}

// fc(D) = 0.5*(cos(pi*D/6)+1) as deg-8 Taylor polynomial in s = D^2
// (entire function of s; max abs err ~1e-6 on [0,36])
__device__ __forceinline__ float fc_poly(float s) {
    float p = 7.626716e-19f;
    p = fmaf(p, s, -6.676529e-16f);
    p = fmaf(p, s, 4.432237e-13f);
    p = fmaf(p, s, -2.134021e-10f);
    p = fmaf(p, s, 7.005500e-8f);
    p = fmaf(p, s, -1.43096781e-5f);
    p = fmaf(p, s, 1.5658612e-3f);
    p = fmaf(p, s, -6.853891945e-2f);
    p = fmaf(p, s, 1.0f);
    return p;
}

// One 512-thread CTA per atom: compaction -> triplet loop -> fused MLP.
__global__ __launch_bounds__(512) void fused_kernel(
    const float* __restrict__ x, int N,
    const float* __restrict__ w1a, const float* __restrict__ b1a,
    const float* __restrict__ w2a, const float* __restrict__ b2a,
    const float* __restrict__ w3a, const float* __restrict__ b3a,
    const float* __restrict__ w1b, const float* __restrict__ b1b,
    const float* __restrict__ w2b, const float* __restrict__ b2b,
    const float* __restrict__ w3b, const float* __restrict__ b3b,
    float* __restrict__ out)
{
    const int i = blockIdx.x;
    __shared__ float4 sU[MAXN + 32];   // {ux, uy, uz, D}
    __shared__ float2 sB[MAXN + 32];   // {D^2, a_ij}
    __shared__ float  sW[1841];        // staged weights (selected net)
    __shared__ int    cnt[16], off[16];
    __shared__ float  red[16], wr[16];
    __shared__ int    Msh;
    __shared__ float  sRad, sAng;
    __shared__ float  sH1[40], sH2[40];

    const int tid  = threadIdx.x;
    const int lane = tid & 31;
    const int w    = tid >> 5;

    // net selection for this atom
    const bool sp = (i == SPECIAL_ATOM);
    const float* W1 = sp ? w1b : w1a;  const float* B1 = sp ? b1b : b1a;
    const float* W2 = sp ? w2b : w2a;  const float* B2 = sp ? b2b : b2a;
    const float* W3 = sp ? w3b : w3a;  const float* B3 = sp ? b3b : b3a;

    // smem weight layout: w1[0:80) b1[80:120) w2(rows stride 41)[120:1760)
    //                     b2[1760:1800) w3[1800:1840) b3[1840]
    auto stage = [&](int t) {
        float v;
        if (t < 80)        v = W1[t];
        else if (t < 120)  v = B1[t - 80];
        else if (t < 1760) { int r = (t - 120) / 41, c = (t - 120) - 41 * r;
                             v = (c < 40) ? W2[r * 40 + c] : 0.f; }
        else if (t < 1800) v = B2[t - 1760];
        else if (t < 1840) v = W3[t - 1800];
        else               v = B3[0];
        sW[t] = v;
    };

    const float xi0 = x[3 * i], xi1 = x[3 * i + 1], xi2 = x[3 * i + 2];
    const int nchunk = (N + 31) >> 5;   // 12 for N=384

    // --- phase 1: warps [0,nchunk) compute one 32-atom chunk each;
    //     spare warps stage the MLP weights (overlapped) ---
    float dx = 0.f, dy = 0.f, dz = 0.f, D = 0.f, inv = 0.f, a = 0.f, D2v = 0.f;
    bool valid = false;
    int rank = 0;
    if (w < nchunk) {
        int j = w * 32 + lane;
        float radp = 0.f;
        float D2 = 1e9f;
        if (j < N) {
            dx = xi0 - x[3 * j];
            dy = xi1 - x[3 * j + 1];
            dz = xi2 - x[3 * j + 2];
            D2 = fmaf(dx, dx, fmaf(dy, dy, dz * dz));
            valid = (j != i) && (D2 <= 36.f);
        }
        unsigned mask = __ballot_sync(0xffffffffu, valid);
        if (valid) {
            inv = rsqrtf(D2);
            D = D2 * inv;
            D2v = D2;
            float fc = fmaf(0.5f, __cosf(0.5235987755982988f * D), 0.5f);
            a = __expf(-0.5f * D2) * fc;           // ETA = 0.5
            float dm = D - 1.f;                     // RS = 1
            radp = __expf(-0.5f * dm * dm) * fc;
            rank = __popc(mask & ((1u << lane) - 1u));
        }
        radp = warp_sum(radp);
        if (lane == 0) { cnt[w] = __popc(mask); red[w] = radp; }
    } else {
        if (lane == 0) { cnt[w] = 0; red[w] = 0.f; }
        const int sbase = tid - nchunk * 32;
        const int sstep = (16 - nchunk) * 32;
        for (int t = sbase; t < 1841; t += sstep) stage(t);
    }
    __syncthreads();

    // --- phase 2: prefix scan of counts + radial total (warp 0) ---
    if (tid < 16) {
        int c = cnt[tid];
        int cs = c;
        #pragma unroll
        for (int d = 1; d < 16; d <<= 1) {
            int t = __shfl_up_sync(0xffffu, cs, d);
            if (tid >= d) cs += t;
        }
        off[tid] = cs - c;
        if (tid == 15) Msh = cs;
        float r = red[tid];
        #pragma unroll
        for (int d = 8; d >= 1; d >>= 1) r += __shfl_down_sync(0xffffu, r, d);
        if (tid == 0) sRad = r;
    }
    __syncthreads();

    // --- phase 3: scatter + sentinel padding ---
    if (valid) {
        int pos = off[w] + rank;
        sU[pos] = make_float4(dx * inv, dy * inv, dz * inv, D);
        sB[pos] = make_float2(D2v, a);
    }
    const int M = Msh;
    const int Mpad = ((M >> 5) + 1) << 5;   // always >= M+1 sentinels
    if (tid < Mpad - M) {
        sU[M + tid] = make_float4(0.f, 0.f, 0.f, 1e3f);
        sB[M + tid] = make_float2(1e6f, 0.f);   // a=0 -> zero contribution
    }
    __syncthreads();

    // --- phase 4: triplet loop; warp w owns rows jj = w, w+16, ... ---
    float accw = 0.f;
    for (int jj = w; jj < M; jj += 16) {
        const float4 uj = sU[jj];
        const float2 bj = sB[jj];
        const float cneg = -2.f * uj.w;
        const float sj = bj.x;
        float accr = 0.f;

        int kk0 = (jj + 1) & ~31;
        const float4* pU = sU + (kk0 + lane);
        const float2* pB = sB + (kk0 + lane);

        // peeled first tile: only lanes with kk > jj contribute
        {
            float4 uk = *pU; float2 bk = *pB;
            float dot  = fmaf(uj.x, uk.x, fmaf(uj.y, uk.y, uj.z * uk.z));
            float t    = fmaf(-0.8f, dot, 1.0f);
            float Djk2 = fmaf(cneg * uk.w, dot, sj + bk.x);
            float zz   = fmaf(0.6f, fast_lg2(t), -0.72134752044448f * Djk2);
            float P    = fast_ex2(zz);
            float p    = fc_poly(Djk2);
            if (kk0 + lane > jj) accr = fmaf(P * p, bk.y, accr);
        }
        // clean tiles: no predicates, no clamps, no cutoff check
        for (kk0 += 32; kk0 < Mpad; kk0 += 32) {
            pU += 32; pB += 32;
            float4 uk = *pU; float2 bk = *pB;
            float dot  = fmaf(uj.x, uk.x, fmaf(uj.y, uk.y, uj.z * uk.z));
            float t    = fmaf(-0.8f, dot, 1.0f);
            float Djk2 = fmaf(cneg * uk.w, dot, sj + bk.x);
            float zz   = fmaf(0.6f, fast_lg2(t), -0.72134752044448f * Djk2);
            float P    = fast_ex2(zz);
            float p    = fc_poly(Djk2);
            accr = fmaf(P * p, bk.y, accr);
        }
        accw = fmaf(bj.y, accr, accw);   // * a_ij
    }

    accw = warp_sum(accw);
    if (lane == 0) wr[w] = accw;
    // fallback weight staging if no spare warps existed (N > 480)
    if (nchunk >= 16) {
        for (int t = tid; t < 1841; t += 512) stage(t);
    }
    __syncthreads();

    if (tid < 16) {
        float s = wr[tid];
        #pragma unroll
        for (int d = 8; d >= 1; d >>= 1) s += __shfl_down_sync(0xffffu, s, d);
        if (tid == 0) sAng = 1.3195079107728942f * s;   // 2^(1-ZETA)
    }
    __syncthreads();

    // --- phase 5: fused MLP (2 -> 40 -> 40 -> 1) ---
    if (tid < 40) {
        float z = fmaf(sW[2 * tid], sAng, fmaf(sW[2 * tid + 1], sRad, sW[80 + tid]));
        sH1[tid] = __fdividef(1.f, fmaf(z, z, 1.f));
    }
    __syncthreads();
    if (tid < 40) {
        float z = sW[1760 + tid];
        const float* row = sW + 120 + tid * 41;
        #pragma unroll 8
        for (int k = 0; k < 40; k++) z = fmaf(row[k], sH1[k], z);
        sH2[tid] = __fdividef(1.f, fmaf(z, z, 1.f));
    }
    __syncthreads();
    if (w == 0) {
        float v = sW[1800 + lane] * sH2[lane];
        if (lane < 8) v = fmaf(sW[1832 + lane], sH2[32 + lane], v);
        v = warp_sum(v);
        if (lane == 0) out[i] = v + sW[1840];
    }
}

extern "C" void kernel_launch(void* const* d_in, const int* in_sizes, int n_in,
                              void* d_out, int out_size) {
    const float* x = (const float*)d_in[0];
    const int N = in_sizes[0] / 3;

    fused_kernel<<<N, 512>>>(
        x, N,
        (const float*)d_in[1],  (const float*)d_in[2],  (const float*)d_in[3],
        (const float*)d_in[4],  (const float*)d_in[5],  (const float*)d_in[6],
        (const float*)d_in[7],  (const float*)d_in[8],  (const float*)d_in[9],
        (const float*)d_in[10], (const float*)d_in[11], (const float*)d_in[12],
        (float*)d_out);
}

// round 7
// speedup vs baseline: 2.6461x; 1.8792x over previous
#include <cuda_runtime.h>

#define MAXN 512
#define SPECIAL_ATOM 8

__device__ float g_rad[MAXN];
__device__ float g_angp[2][MAXN];

__device__ __forceinline__ float warp_sum(float v) {
    v += __shfl_down_sync(0xffffffffu, v, 16);
    v += __shfl_down_sync(0xffffffffu, v, 8);
    v += __shfl_down_sync(0xffffffffu, v, 4);
    v += __shfl_down_sync(0xffffffffu, v, 2);
    v += __shfl_down_sync(0xffffffffu, v, 1);
    return v;
}

__device__ __forceinline__ float fast_lg2(float x) {
    float r; asm("lg2.approx.ftz.f32 %0, %1;" : "=f"(r) : "f"(x)); return r;
}
__device__ __forceinline__ float fast_ex2(float x) {
    float r; asm("ex2.approx.ftz.f32 %0, %1;" : "=f"(r) : "f"(x)); return r;
}

// fc(D)=0.5*(cos(pi*D/6)+1) as deg-5 Taylor in s=D^2; error weighted by the
// fused exp(-0.7213*s) factor stays <~1e-6 everywhere it matters.
__device__ __forceinline__ float fc_poly(float s) {
    float p = -2.133e-10f;
    p = fmaf(p, s, 7.00553e-8f);
    p = fmaf(p, s, -1.430964e-5f);
    p = fmaf(p, s, 1.565855e-3f);
    p = fmaf(p, s, -6.8538918e-2f);
    p = fmaf(p, s, 1.0f);
    return p;
}

// K1: 2 CTAs per atom (256 threads each). Compaction -> row-pair triplet loop.
__global__ __launch_bounds__(256, 6) void tri_kernel(const float* __restrict__ x, int N) {
    const int i    = blockIdx.x >> 1;
    const int half = blockIdx.x & 1;
    __shared__ float4 sU[MAXN + 32];
    __shared__ float2 sB[MAXN + 32];
    __shared__ int   cnt[16], off[16];
    __shared__ float red[8], wr[8];
    __shared__ int   Msh;

    const int tid  = threadIdx.x;
    const int lane = tid & 31;
    const int w    = tid >> 5;

    const float xi0 = x[3 * i], xi1 = x[3 * i + 1], xi2 = x[3 * i + 2];

    // --- phase 1: 8 warps x 2 chunk passes over N atoms ---
    bool  ev[2];  int erank[2]; int echunk[2];
    float eux[2], euy[2], euz[2], eD[2], eD2[2], ea[2];
    float rad = 0.f;
    #pragma unroll
    for (int pass = 0; pass < 2; pass++) {
        const int c = w + 8 * pass;     // chunk 0..15
        const int j = c * 32 + lane;
        float dx = 0.f, dy = 0.f, dz = 0.f, D2 = 1e9f;
        bool valid = false;
        if (j < N) {
            dx = xi0 - x[3 * j];
            dy = xi1 - x[3 * j + 1];
            dz = xi2 - x[3 * j + 2];
            D2 = fmaf(dx, dx, fmaf(dy, dy, dz * dz));
            valid = (j != i) && (D2 <= 36.f);
        }
        unsigned mask = __ballot_sync(0xffffffffu, valid);
        ev[pass] = valid; echunk[pass] = c;
        erank[pass] = __popc(mask & ((1u << lane) - 1u));
        if (valid) {
            float inv = rsqrtf(D2);
            float D = D2 * inv;
            float fc = fmaf(0.5f, __cosf(0.5235987755982988f * D), 0.5f);
            float a = __expf(-0.5f * D2) * fc;
            float dm = D - 1.f;
            rad += __expf(-0.5f * dm * dm) * fc;
            eux[pass] = dx * inv; euy[pass] = dy * inv; euz[pass] = dz * inv;
            eD[pass] = D; eD2[pass] = D2; ea[pass] = a;
        }
        if (lane == 0) cnt[c] = __popc(mask);
    }
    rad = warp_sum(rad);
    if (lane == 0) red[w] = rad;
    __syncthreads();

    // --- phase 2: prefix scan over 16 chunk counts; radial total ---
    if (tid < 16) {
        int c = cnt[tid];
        int cs = c;
        #pragma unroll
        for (int d = 1; d < 16; d <<= 1) {
            int t = __shfl_up_sync(0xffffu, cs, d);
            if (tid >= d) cs += t;
        }
        off[tid] = cs - c;
        if (tid == 15) Msh = cs;
        if (tid < 8) {
            float r = red[tid];
            #pragma unroll
            for (int d = 4; d >= 1; d >>= 1) r += __shfl_down_sync(0xffu, r, d);
            if (tid == 0 && half == 0) g_rad[i] = r;
        }
    }
    __syncthreads();

    // --- phase 3: scatter + sentinels ---
    #pragma unroll
    for (int pass = 0; pass < 2; pass++) {
        if (ev[pass]) {
            int pos = off[echunk[pass]] + erank[pass];
            sU[pos] = make_float4(eux[pass], euy[pass], euz[pass], eD[pass]);
            sB[pos] = make_float2(eD2[pass], ea[pass]);
        }
    }
    const int M = Msh;
    const int Mpad = ((M >> 5) + 1) << 5;      // >= M+1 sentinels
    if (tid < Mpad - M) {
        sU[M + tid] = make_float4(0.f, 0.f, 0.f, 1e3f);
        sB[M + tid] = make_float2(1e6f, 0.f);  // a = 0 -> exact zero contribution
    }
    __syncthreads();

    // --- phase 4: row-pair triplet loop. global warp g owns pairs (2g+32t, +1) ---
    const int g = half * 8 + w;
    float accw = 0.f;
    for (int j0 = 2 * g; j0 < M; j0 += 32) {
        const int j1 = j0 + 1;
        const int j1c = (j1 < M) ? j1 : M;     // sentinel row if beyond
        const float4 uj0 = sU[j0];  const float2 bj0 = sB[j0];
        const float4 uj1 = sU[j1c]; const float2 bj1 = sB[j1c];
        const float cn0 = -2.f * uj0.w, s0 = bj0.x;
        const float cn1 = -2.f * uj1.w, s1 = bj1.x;
        float a0 = 0.f, a1 = 0.f;

        const int tpred = (j0 + 1) & ~31;
        const int tclean = (j1c + 32) & ~31;   // align_up(j1c+1) <= Mpad

        for (int t = tpred; t < tclean; t += 32) {
            const int kk = t + lane;
            float4 uk = sU[kk]; float2 bk = sB[kk];
            float d0 = fmaf(uj0.x, uk.x, fmaf(uj0.y, uk.y, uj0.z * uk.z));
            float t0 = fmaf(-0.8f, d0, 1.0f);
            float q0 = fmaf(cn0 * uk.w, d0, s0 + bk.x);
            float P0 = fast_ex2(fmaf(-0.72134752044448f, q0, 0.6f * fast_lg2(t0)));
            if (kk > j0) a0 = fmaf(P0 * fc_poly(q0), bk.y, a0);
            float d1 = fmaf(uj1.x, uk.x, fmaf(uj1.y, uk.y, uj1.z * uk.z));
            float t1 = fmaf(-0.8f, d1, 1.0f);
            float q1 = fmaf(cn1 * uk.w, d1, s1 + bk.x);
            float P1 = fast_ex2(fmaf(-0.72134752044448f, q1, 0.6f * fast_lg2(t1)));
            if (kk > j1c) a1 = fmaf(P1 * fc_poly(q1), bk.y, a1);
        }
        for (int t = tclean; t < Mpad; t += 32) {
            const int kk = t + lane;
            float4 uk = sU[kk]; float2 bk = sB[kk];
            float d0 = fmaf(uj0.x, uk.x, fmaf(uj0.y, uk.y, uj0.z * uk.z));
            float t0 = fmaf(-0.8f, d0, 1.0f);
            float q0 = fmaf(cn0 * uk.w, d0, s0 + bk.x);
            float P0 = fast_ex2(fmaf(-0.72134752044448f, q0, 0.6f * fast_lg2(t0)));
            a0 = fmaf(P0 * fc_poly(q0), bk.y, a0);
            float d1 = fmaf(uj1.x, uk.x, fmaf(uj1.y, uk.y, uj1.z * uk.z));
            float t1 = fmaf(-0.8f, d1, 1.0f);
            float q1 = fmaf(cn1 * uk.w, d1, s1 + bk.x);
            float P1 = fast_ex2(fmaf(-0.72134752044448f, q1, 0.6f * fast_lg2(t1)));
            a1 = fmaf(P1 * fc_poly(q1), bk.y, a1);
        }
        accw = fmaf(bj0.y, a0, accw);
        accw = fmaf(bj1.y, a1, accw);   // bj1.y = 0 for sentinel row
    }

    accw = warp_sum(accw);
    if (lane == 0) wr[w] = accw;
    __syncthreads();
    if (tid < 8) {
        float s = wr[tid];
        #pragma unroll
        for (int d = 4; d >= 1; d >>= 1) s += __shfl_down_sync(0xffu, s, d);
        if (tid == 0) g_angp[half][i] = s;
    }
}

// K2: MLPs, warp-per-atom, 8 atoms per 256-thread CTA, both nets in smem.
__global__ __launch_bounds__(256) void mlp_kernel(
    const float* __restrict__ w1a, const float* __restrict__ b1a,
    const float* __restrict__ w2a, const float* __restrict__ b2a,
    const float* __restrict__ w3a, const float* __restrict__ b3a,
    const float* __restrict__ w1b, const float* __restrict__ b1b,
    const float* __restrict__ w2b, const float* __restrict__ b2b,
    const float* __restrict__ w3b, const float* __restrict__ b3b,
    float* __restrict__ out, int N)
{
    // per-net layout: w1[0:80) b1[80:120) w2 rows stride 41 [120:1760)
    //                 b2[1760:1800) w3[1800:1840) b3[1840]; size 1841
    __shared__ float sW[2 * 1841];
    __shared__ float sH1[8][40];
    __shared__ float sH2[8][40];
    const int tid = threadIdx.x;
    const int lane = tid & 31;
    const int w = tid >> 5;

    for (int t = tid; t < 1841; t += 256) {
        float va, vb;
        if (t < 80)        { va = w1a[t];        vb = w1b[t]; }
        else if (t < 120)  { va = b1a[t - 80];   vb = b1b[t - 80]; }
        else if (t < 1760) { int r = (t - 120) / 41, c = (t - 120) - 41 * r;
                             va = (c < 40) ? w2a[r * 40 + c] : 0.f;
                             vb = (c < 40) ? w2b[r * 40 + c] : 0.f; }
        else if (t < 1800) { va = b2a[t - 1760]; vb = b2b[t - 1760]; }
        else if (t < 1840) { va = w3a[t - 1800]; vb = w3b[t - 1800]; }
        else               { va = b3a[0];        vb = b3b[0]; }
        sW[t] = va; sW[1841 + t] = vb;
    }
    __syncthreads();

    const int i = blockIdx.x * 8 + w;
    if (i >= N) return;
    const float* W = sW + ((i == SPECIAL_ATOM) ? 1841 : 0);
    const float g0 = 1.3195079107728942f * (g_angp[0][i] + g_angp[1][i]);
    const float g1 = g_rad[i];

    // layer 1: 40 outputs over 2 lane passes
    #pragma unroll
    for (int p = 0; p < 2; p++) {
        int o = lane + 32 * p;
        if (o < 40) {
            float z = fmaf(W[2 * o], g0, fmaf(W[2 * o + 1], g1, W[80 + o]));
            sH1[w][o] = __fdividef(1.f, fmaf(z, z, 1.f));
        }
    }
    __syncwarp();
    // layer 2
    #pragma unroll
    for (int p = 0; p < 2; p++) {
        int o = lane + 32 * p;
        if (o < 40) {
            float z = W[1760 + o];
            const float* row = W + 120 + o * 41;
            #pragma unroll 8
            for (int k = 0; k < 40; k++) z = fmaf(row[k], sH1[w][k], z);
            sH2[w][o] = __fdividef(1.f, fmaf(z, z, 1.f));
        }
    }
    __syncwarp();
    // layer 3
    float v = W[1800 + lane] * sH2[w][lane];
    if (lane < 8) v = fmaf(W[1832 + lane], sH2[w][32 + lane], v);
    v = warp_sum(v);
    if (lane == 0) out[i] = v + W[1840];
}

extern "C" void kernel_launch(void* const* d_in, const int* in_sizes, int n_in,
                              void* d_out, int out_size) {
    const float* x = (const float*)d_in[0];
    const int N = in_sizes[0] / 3;

    tri_kernel<<<2 * N, 256>>>(x, N);

    const int grid = (N + 7) / 8;
    mlp_kernel<<<grid, 256>>>(
        (const float*)d_in[1],  (const float*)d_in[2],  (const float*)d_in[3],
        (const float*)d_in[4],  (const float*)d_in[5],  (const float*)d_in[6],
        (const float*)d_in[7],  (const float*)d_in[8],  (const float*)d_in[9],
        (const float*)d_in[10], (const float*)d_in[11], (const float*)d_in[12],
        (float*)d_out, N);
}

// round 8
// speedup vs baseline: 2.9721x; 1.1232x over previous
#include <cuda_runtime.h>

#define MAXN 512
#define SPECIAL_ATOM 8

__device__ __forceinline__ float warp_sum(float v) {
    v += __shfl_down_sync(0xffffffffu, v, 16);
    v += __shfl_down_sync(0xffffffffu, v, 8);
    v += __shfl_down_sync(0xffffffffu, v, 4);
    v += __shfl_down_sync(0xffffffffu, v, 2);
    v += __shfl_down_sync(0xffffffffu, v, 1);
    return v;
}

__device__ __forceinline__ float fast_lg2(float x) {
    float r; asm("lg2.approx.ftz.f32 %0, %1;" : "=f"(r) : "f"(x)); return r;
}
__device__ __forceinline__ float fast_ex2(float x) {
    float r; asm("ex2.approx.ftz.f32 %0, %1;" : "=f"(r) : "f"(x)); return r;
}

// fc(D)=0.5*(cos(pi*D/6)+1) as deg-5 Taylor in s=D^2; error weighted by the
// fused exp(-0.7213*s) factor stays <~1e-6 everywhere it matters.
__device__ __forceinline__ float fc_poly(float s) {
    float p = -2.133e-10f;
    p = fmaf(p, s, 7.00553e-8f);
    p = fmaf(p, s, -1.430964e-5f);
    p = fmaf(p, s, 1.565855e-3f);
    p = fmaf(p, s, -6.8538918e-2f);
    p = fmaf(p, s, 1.0f);
    return p;
}

// ONE 256-thread CTA per atom: compaction -> 4-row triplet loop -> fused MLP.
__global__ __launch_bounds__(256, 4) void fused_kernel(
    const float* __restrict__ x, int N,
    const float* __restrict__ w1a, const float* __restrict__ b1a,
    const float* __restrict__ w2a, const float* __restrict__ b2a,
    const float* __restrict__ w3a, const float* __restrict__ b3a,
    const float* __restrict__ w1b, const float* __restrict__ b1b,
    const float* __restrict__ w2b, const float* __restrict__ b2b,
    const float* __restrict__ w3b, const float* __restrict__ b3b,
    float* __restrict__ out)
{
    const int i = blockIdx.x;
    __shared__ float4 sU[MAXN + 32];   // {ux, uy, uz, D}
    __shared__ float2 sB[MAXN + 32];   // {D^2, a_ij}
    __shared__ float  sW[1841];        // staged weights (selected net)
    __shared__ int    cnt[16], off[16];
    __shared__ float  red[8], wr[8];
    __shared__ int    Msh;
    __shared__ float  sRad, sAng, sH1[40], sH2[40];

    const int tid  = threadIdx.x;
    const int lane = tid & 31;
    const int w    = tid >> 5;

    const bool sp = (i == SPECIAL_ATOM);
    const float* W1 = sp ? w1b : w1a;  const float* B1 = sp ? b1b : b1a;
    const float* W2 = sp ? w2b : w2a;  const float* B2 = sp ? b2b : b2a;
    const float* W3 = sp ? w3b : w3a;  const float* B3 = sp ? b3b : b3a;

    const float xi0 = x[3 * i], xi1 = x[3 * i + 1], xi2 = x[3 * i + 2];

    // --- phase 1: 8 warps x 2 passes cover 16 chunks of 32 atoms ---
    bool  ev[2];  int erank[2];
    float eux[2], euy[2], euz[2], eD[2], eD2[2], ea[2];
    float rad = 0.f;
    #pragma unroll
    for (int pass = 0; pass < 2; pass++) {
        const int c = w + 8 * pass;
        const int j = c * 32 + lane;
        float dx = 0.f, dy = 0.f, dz = 0.f, D2 = 1e9f;
        bool valid = false;
        if (j < N) {
            dx = xi0 - x[3 * j];
            dy = xi1 - x[3 * j + 1];
            dz = xi2 - x[3 * j + 2];
            D2 = fmaf(dx, dx, fmaf(dy, dy, dz * dz));
            valid = (j != i) && (D2 <= 36.f);
        }
        unsigned mask = __ballot_sync(0xffffffffu, valid);
        ev[pass] = valid;
        erank[pass] = __popc(mask & ((1u << lane) - 1u));
        if (valid) {
            float inv = rsqrtf(D2);
            float D = D2 * inv;
            float fc = fmaf(0.5f, __cosf(0.5235987755982988f * D), 0.5f);
            float a = __expf(-0.5f * D2) * fc;     // ETA = 0.5
            float dm = D - 1.f;                     // RS = 1
            rad += __expf(-0.5f * dm * dm) * fc;
            eux[pass] = dx * inv; euy[pass] = dy * inv; euz[pass] = dz * inv;
            eD[pass] = D; eD2[pass] = D2; ea[pass] = a;
        }
        if (lane == 0) cnt[c] = __popc(mask);
    }
    rad = warp_sum(rad);
    if (lane == 0) red[w] = rad;
    __syncthreads();

    // --- phase 2: prefix scan of 16 chunk counts + radial total ---
    if (tid < 16) {
        int c = cnt[tid];
        int cs = c;
        #pragma unroll
        for (int d = 1; d < 16; d <<= 1) {
            int t = __shfl_up_sync(0xffffu, cs, d);
            if (tid >= d) cs += t;
        }
        off[tid] = cs - c;
        if (tid == 15) Msh = cs;
        if (tid < 8) {
            float r = red[tid];
            #pragma unroll
            for (int d = 4; d >= 1; d >>= 1) r += __shfl_down_sync(0xffu, r, d);
            if (tid == 0) sRad = r;
        }
    }
    __syncthreads();

    // --- phase 3: scatter + sentinels ---
    #pragma unroll
    for (int pass = 0; pass < 2; pass++) {
        if (ev[pass]) {
            int pos = off[w + 8 * pass] + erank[pass];
            sU[pos] = make_float4(eux[pass], euy[pass], euz[pass], eD[pass]);
            sB[pos] = make_float2(eD2[pass], ea[pass]);
        }
    }
    const int M = Msh;
    const int Mpad = ((M >> 5) + 1) << 5;      // >= M+1 sentinels
    if (tid < Mpad - M) {
        sU[M + tid] = make_float4(0.f, 0.f, 0.f, 1e3f);
        sB[M + tid] = make_float2(1e6f, 0.f);  // a = 0 -> exact zero contribution
    }
    __syncthreads();

    // --- phase 4: 4-row triplet loop. warp w owns rows {4w+32t .. +3} ---
    float accw = 0.f;
    for (int j0 = 4 * w; j0 < M; j0 += 32) {
        const int j1 = (j0 + 1 < M) ? j0 + 1 : M;   // sentinel redirect (a=0)
        const int j2 = (j0 + 2 < M) ? j0 + 2 : M;
        const int j3 = (j0 + 3 < M) ? j0 + 3 : M;
        const float4 u0 = sU[j0], u1 = sU[j1], u2 = sU[j2], u3 = sU[j3];
        const float2 b0 = sB[j0], b1 = sB[j1], b2 = sB[j2], b3 = sB[j3];
        const float c0 = -2.f * u0.w, c1 = -2.f * u1.w, c2 = -2.f * u2.w, c3 = -2.f * u3.w;
        float a0 = 0.f, a1 = 0.f, a2 = 0.f, a3 = 0.f;

        const int t0 = j0 & ~31;       // the single tile containing j0..j3
        // predicated tile
        {
            const int kk = t0 + lane;
            float4 uk = sU[kk]; float2 bk = sB[kk];
            float d, t, q, P;
            d = fmaf(u0.x, uk.x, fmaf(u0.y, uk.y, u0.z * uk.z));
            t = fmaf(-0.8f, d, 1.0f);
            q = fmaf(c0 * uk.w, d, b0.x + bk.x);
            P = fast_ex2(fmaf(-0.72134752044448f, q, 0.6f * fast_lg2(t)));
            if (kk > j0) a0 = fmaf(P * fc_poly(q), bk.y, a0);
            d = fmaf(u1.x, uk.x, fmaf(u1.y, uk.y, u1.z * uk.z));
            t = fmaf(-0.8f, d, 1.0f);
            q = fmaf(c1 * uk.w, d, b1.x + bk.x);
            P = fast_ex2(fmaf(-0.72134752044448f, q, 0.6f * fast_lg2(t)));
            if (kk > j1) a1 = fmaf(P * fc_poly(q), bk.y, a1);
            d = fmaf(u2.x, uk.x, fmaf(u2.y, uk.y, u2.z * uk.z));
            t = fmaf(-0.8f, d, 1.0f);
            q = fmaf(c2 * uk.w, d, b2.x + bk.x);
            P = fast_ex2(fmaf(-0.72134752044448f, q, 0.6f * fast_lg2(t)));
            if (kk > j2) a2 = fmaf(P * fc_poly(q), bk.y, a2);
            d = fmaf(u3.x, uk.x, fmaf(u3.y, uk.y, u3.z * uk.z));
            t = fmaf(-0.8f, d, 1.0f);
            q = fmaf(c3 * uk.w, d, b3.x + bk.x);
            P = fast_ex2(fmaf(-0.72134752044448f, q, 0.6f * fast_lg2(t)));
            if (kk > j3) a3 = fmaf(P * fc_poly(q), bk.y, a3);
        }
        // clean tiles
        for (int tt = t0 + 32; tt < Mpad; tt += 32) {
            const int kk = tt + lane;
            float4 uk = sU[kk]; float2 bk = sB[kk];
            float d, t, q, P;
            d = fmaf(u0.x, uk.x, fmaf(u0.y, uk.y, u0.z * uk.z));
            t = fmaf(-0.8f, d, 1.0f);
            q = fmaf(c0 * uk.w, d, b0.x + bk.x);
            P = fast_ex2(fmaf(-0.72134752044448f, q, 0.6f * fast_lg2(t)));
            a0 = fmaf(P * fc_poly(q), bk.y, a0);
            d = fmaf(u1.x, uk.x, fmaf(u1.y, uk.y, u1.z * uk.z));
            t = fmaf(-0.8f, d, 1.0f);
            q = fmaf(c1 * uk.w, d, b1.x + bk.x);
            P = fast_ex2(fmaf(-0.72134752044448f, q, 0.6f * fast_lg2(t)));
            a1 = fmaf(P * fc_poly(q), bk.y, a1);
            d = fmaf(u2.x, uk.x, fmaf(u2.y, uk.y, u2.z * uk.z));
            t = fmaf(-0.8f, d, 1.0f);
            q = fmaf(c2 * uk.w, d, b2.x + bk.x);
            P = fast_ex2(fmaf(-0.72134752044448f, q, 0.6f * fast_lg2(t)));
            a2 = fmaf(P * fc_poly(q), bk.y, a2);
            d = fmaf(u3.x, uk.x, fmaf(u3.y, uk.y, u3.z * uk.z));
            t = fmaf(-0.8f, d, 1.0f);
            q = fmaf(c3 * uk.w, d, b3.x + bk.x);
            P = fast_ex2(fmaf(-0.72134752044448f, q, 0.6f * fast_lg2(t)));
            a3 = fmaf(P * fc_poly(q), bk.y, a3);
        }
        accw = fmaf(b0.y, a0, accw);
        accw = fmaf(b1.y, a1, accw);
        accw = fmaf(b2.y, a2, accw);
        accw = fmaf(b3.y, a3, accw);
    }

    accw = warp_sum(accw);
    if (lane == 0) wr[w] = accw;

    // --- stage MLP weights (overlaps inter-warp skew before the barrier) ---
    // layout: w1[0:80) b1[80:120) w2 rows stride 41 [120:1760)
    //         b2[1760:1800) w3[1800:1840) b3[1840]
    for (int t = tid; t < 1841; t += 256) {
        float v;
        if (t < 80)        v = W1[t];
        else if (t < 120)  v = B1[t - 80];
        else if (t < 1760) { int r = (t - 120) / 41, c = (t - 120) - 41 * r;
                             v = (c < 40) ? W2[r * 40 + c] : 0.f; }
        else if (t < 1800) v = B2[t - 1760];
        else if (t < 1840) v = W3[t - 1800];
        else               v = B3[0];
        sW[t] = v;
    }
    __syncthreads();

    if (tid < 8) {
        float s = wr[tid];
        #pragma unroll
        for (int d = 4; d >= 1; d >>= 1) s += __shfl_down_sync(0xffu, s, d);
        if (tid == 0) sAng = 1.3195079107728942f * s;   // 2^(1-ZETA)
    }
    __syncthreads();

    // --- fused MLP (2 -> 40 -> 40 -> 1) ---
    if (tid < 40) {
        float z = fmaf(sW[2 * tid], sAng, fmaf(sW[2 * tid + 1], sRad, sW[80 + tid]));
        sH1[tid] = __fdividef(1.f, fmaf(z, z, 1.f));
    }
    __syncthreads();
    if (tid < 40) {
        float z = sW[1760 + tid];
        const float* row = sW + 120 + tid * 41;
        #pragma unroll 8
        for (int k = 0; k < 40; k++) z = fmaf(row[k], sH1[k], z);
        sH2[tid] = __fdividef(1.f, fmaf(z, z, 1.f));
    }
    __syncthreads();
    if (w == 0) {
        float v = sW[1800 + lane] * sH2[lane];
        if (lane < 8) v = fmaf(sW[1832 + lane], sH2[32 + lane], v);
        v = warp_sum(v);
        if (lane == 0) out[i] = v + sW[1840];
    }
}

extern "C" void kernel_launch(void* const* d_in, const int* in_sizes, int n_in,
                              void* d_out, int out_size) {
    const float* x = (const float*)d_in[0];
    const int N = in_sizes[0] / 3;

    fused_kernel<<<N, 256>>>(
        x, N,
        (const float*)d_in[1],  (const float*)d_in[2],  (const float*)d_in[3],
        (const float*)d_in[4],  (const float*)d_in[5],  (const float*)d_in[6],
        (const float*)d_in[7],  (const float*)d_in[8],  (const float*)d_in[9],
        (const float*)d_in[10], (const float*)d_in[11], (const float*)d_in[12],
        (float*)d_out);
}

// round 10
// speedup vs baseline: 3.0010x; 1.0097x over previous
#include <cuda_runtime.h>

#define MAXN 512
#define SPECIAL_ATOM 8

typedef unsigned long long ull;

__device__ __forceinline__ float warp_sum(float v) {
    v += __shfl_down_sync(0xffffffffu, v, 16);
    v += __shfl_down_sync(0xffffffffu, v, 8);
    v += __shfl_down_sync(0xffffffffu, v, 4);
    v += __shfl_down_sync(0xffffffffu, v, 2);
    v += __shfl_down_sync(0xffffffffu, v, 1);
    return v;
}

__device__ __forceinline__ float fast_lg2(float x) {
    float r; asm("lg2.approx.ftz.f32 %0, %1;" : "=f"(r) : "f"(x)); return r;
}
__device__ __forceinline__ float fast_ex2(float x) {
    float r; asm("ex2.approx.ftz.f32 %0, %1;" : "=f"(r) : "f"(x)); return r;
}

// ---- packed f32x2 helpers (FFMA2 path, PTX-only on sm_103a) ----
__device__ __forceinline__ ull pack2(float lo, float hi) {
    ull r; asm("mov.b64 %0, {%1, %2};" : "=l"(r) : "f"(lo), "f"(hi)); return r;
}
__device__ __forceinline__ ull dup2(float v) {
    ull r; asm("mov.b64 %0, {%1, %1};" : "=l"(r) : "f"(v)); return r;
}
__device__ __forceinline__ void unpack2(ull v, float& lo, float& hi) {
    asm("mov.b64 {%0, %1}, %2;" : "=f"(lo), "=f"(hi) : "l"(v));
}
__device__ __forceinline__ ull fma2(ull a, ull b, ull c) {
    ull d; asm("fma.rn.f32x2 %0, %1, %2, %3;" : "=l"(d) : "l"(a), "l"(b), "l"(c)); return d;
}
__device__ __forceinline__ ull mul2(ull a, ull b) {
    ull d; asm("mul.rn.f32x2 %0, %1, %2;" : "=l"(d) : "l"(a), "l"(b)); return d;
}
__device__ __forceinline__ ull add2(ull a, ull b) {
    ull d; asm("add.rn.f32x2 %0, %1, %2;" : "=l"(d) : "l"(a), "l"(b)); return d;
}

// fc(D)=0.5*(cos(pi*D/6)+1) deg-5 Taylor in s=D^2 (scalar, for peel/compaction)
__device__ __forceinline__ float fc_poly(float s) {
    float p = -2.133e-10f;
    p = fmaf(p, s, 7.00553e-8f);
    p = fmaf(p, s, -1.430964e-5f);
    p = fmaf(p, s, 1.565855e-3f);
    p = fmaf(p, s, -6.8538918e-2f);
    p = fmaf(p, s, 1.0f);
    return p;
}

// ONE 256-thread CTA per atom: compaction -> packed 4-row triplet loop -> fused MLP.
__global__ __launch_bounds__(256, 3) void fused_kernel(
    const float* __restrict__ x, int N,
    const float* __restrict__ w1a, const float* __restrict__ b1a,
    const float* __restrict__ w2a, const float* __restrict__ b2a,
    const float* __restrict__ w3a, const float* __restrict__ b3a,
    const float* __restrict__ w1b, const float* __restrict__ b1b,
    const float* __restrict__ w2b, const float* __restrict__ b2b,
    const float* __restrict__ w3b, const float* __restrict__ b3b,
    float* __restrict__ out)
{
    const int i = blockIdx.x;
    __shared__ float4 sU[MAXN + 32];   // {ux, uy, uz, D}
    __shared__ float2 sB[MAXN + 32];   // {D^2, a_ij}
    __shared__ float  sW[1841];
    __shared__ int    cnt[16], off[16];
    __shared__ float  red[8], wr[8];
    __shared__ int    Msh;
    __shared__ float  sRad, sAng, sH1[40], sH2[40];

    const int tid  = threadIdx.x;
    const int lane = tid & 31;
    const int w    = tid >> 5;

    const bool sp = (i == SPECIAL_ATOM);
    const float* W1 = sp ? w1b : w1a;  const float* B1 = sp ? b1b : b1a;
    const float* W2 = sp ? w2b : w2a;  const float* B2 = sp ? b2b : b2a;
    const float* W3 = sp ? w3b : w3a;  const float* B3 = sp ? b3b : b3a;

    const float xi0 = x[3 * i], xi1 = x[3 * i + 1], xi2 = x[3 * i + 2];

    // --- phase 1: 8 warps x 2 passes cover 16 chunks of 32 atoms ---
    bool  ev[2];  int erank[2];
    float eux[2], euy[2], euz[2], eD[2], eD2[2], ea[2];
    float rad = 0.f;
    #pragma unroll
    for (int pass = 0; pass < 2; pass++) {
        const int c = w + 8 * pass;
        const int j = c * 32 + lane;
        float dx = 0.f, dy = 0.f, dz = 0.f, D2 = 1e9f;
        bool valid = false;
        if (j < N) {
            dx = xi0 - x[3 * j];
            dy = xi1 - x[3 * j + 1];
            dz = xi2 - x[3 * j + 2];
            D2 = fmaf(dx, dx, fmaf(dy, dy, dz * dz));
            valid = (j != i) && (D2 <= 36.f);
        }
        unsigned mask = __ballot_sync(0xffffffffu, valid);
        ev[pass] = valid;
        erank[pass] = __popc(mask & ((1u << lane) - 1u));
        if (valid) {
            float inv = rsqrtf(D2);
            float D = D2 * inv;
            float fc = fmaf(0.5f, __cosf(0.5235987755982988f * D), 0.5f);
            float a = __expf(-0.5f * D2) * fc;     // ETA = 0.5
            float dm = D - 1.f;                     // RS = 1
            rad += __expf(-0.5f * dm * dm) * fc;
            eux[pass] = dx * inv; euy[pass] = dy * inv; euz[pass] = dz * inv;
            eD[pass] = D; eD2[pass] = D2; ea[pass] = a;
        }
        if (lane == 0) cnt[c] = __popc(mask);
    }
    rad = warp_sum(rad);
    if (lane == 0) red[w] = rad;
    __syncthreads();

    // --- phase 2: prefix scan + radial total ---
    if (tid < 16) {
        int c = cnt[tid];
        int cs = c;
        #pragma unroll
        for (int d = 1; d < 16; d <<= 1) {
            int t = __shfl_up_sync(0xffffu, cs, d);
            if (tid >= d) cs += t;
        }
        off[tid] = cs - c;
        if (tid == 15) Msh = cs;
        if (tid < 8) {
            float r = red[tid];
            #pragma unroll
            for (int d = 4; d >= 1; d >>= 1) r += __shfl_down_sync(0xffu, r, d);
            if (tid == 0) sRad = r;
        }
    }
    __syncthreads();

    // --- phase 3: scatter + sentinels ---
    #pragma unroll
    for (int pass = 0; pass < 2; pass++) {
        if (ev[pass]) {
            int pos = off[w + 8 * pass] + erank[pass];
            sU[pos] = make_float4(eux[pass], euy[pass], euz[pass], eD[pass]);
            sB[pos] = make_float2(eD2[pass], ea[pass]);
        }
    }
    const int M = Msh;
    const int Mpad = ((M >> 5) + 1) << 5;      // >= M+1 sentinels
    if (tid < Mpad - M) {
        sU[M + tid] = make_float4(0.f, 0.f, 0.f, 1e3f);
        sB[M + tid] = make_float2(1e6f, 0.f);  // a = 0 -> exact zero contribution
    }
    __syncthreads();

    // packed constants
    const ull K1   = dup2(1.0f);
    const ull KN08 = dup2(-0.8f);
    const ull K06  = dup2(0.6f);
    const ull KNE  = dup2(-0.72134752044448f);
    const ull PC5  = dup2(-2.133e-10f);
    const ull PC4  = dup2(7.00553e-8f);
    const ull PC3  = dup2(-1.430964e-5f);
    const ull PC2  = dup2(1.565855e-3f);
    const ull PC1  = dup2(-6.8538918e-2f);

    // --- phase 4: packed 4-row triplet loop; warp w owns rows {4w+32t..+3} ---
    float accw = 0.f;
    for (int j0 = 4 * w; j0 < M; j0 += 32) {
        const int j1 = (j0 + 1 < M) ? j0 + 1 : M;   // sentinel redirect (a=0)
        const int j2 = (j0 + 2 < M) ? j0 + 2 : M;
        const int j3 = (j0 + 3 < M) ? j0 + 3 : M;
        const float4 u0 = sU[j0], u1 = sU[j1], u2 = sU[j2], u3 = sU[j3];
        const float2 b0 = sB[j0], b1 = sB[j1], b2 = sB[j2], b3 = sB[j3];

        // pair A = (j0, j1), pair B = (j2, j3)
        const ull uxA = pack2(u0.x, u1.x), uxB = pack2(u2.x, u3.x);
        const ull uyA = pack2(u0.y, u1.y), uyB = pack2(u2.y, u3.y);
        const ull uzA = pack2(u0.z, u1.z), uzB = pack2(u2.z, u3.z);
        const ull cA  = pack2(-2.f * u0.w, -2.f * u1.w);
        const ull cB  = pack2(-2.f * u2.w, -2.f * u3.w);
        const ull sA  = pack2(b0.x, b1.x), sB2 = pack2(b2.x, b3.x);
        ull accA = 0, accB = 0;   // packed {0,0}

        const int t0 = j0 & ~31;
        // ---- peel tile (scalar, predicated) ----
        {
            const int kk = t0 + lane;
            float4 uk = sU[kk]; float2 bk = sB[kk];
            float aa0 = 0.f, aa1 = 0.f, aa2 = 0.f, aa3 = 0.f;
            float d, t, q, P;
            d = fmaf(u0.x, uk.x, fmaf(u0.y, uk.y, u0.z * uk.z));
            t = fmaf(-0.8f, d, 1.0f);
            q = fmaf(-2.f * u0.w * uk.w, d, b0.x + bk.x);
            P = fast_ex2(fmaf(-0.72134752044448f, q, 0.6f * fast_lg2(t)));
            if (kk > j0) aa0 = P * fc_poly(q) * bk.y;
            d = fmaf(u1.x, uk.x, fmaf(u1.y, uk.y, u1.z * uk.z));
            t = fmaf(-0.8f, d, 1.0f);
            q = fmaf(-2.f * u1.w * uk.w, d, b1.x + bk.x);
            P = fast_ex2(fmaf(-0.72134752044448f, q, 0.6f * fast_lg2(t)));
            if (kk > j1) aa1 = P * fc_poly(q) * bk.y;
            d = fmaf(u2.x, uk.x, fmaf(u2.y, uk.y, u2.z * uk.z));
            t = fmaf(-0.8f, d, 1.0f);
            q = fmaf(-2.f * u2.w * uk.w, d, b2.x + bk.x);
            P = fast_ex2(fmaf(-0.72134752044448f, q, 0.6f * fast_lg2(t)));
            if (kk > j2) aa2 = P * fc_poly(q) * bk.y;
            d = fmaf(u3.x, uk.x, fmaf(u3.y, uk.y, u3.z * uk.z));
            t = fmaf(-0.8f, d, 1.0f);
            q = fmaf(-2.f * u3.w * uk.w, d, b3.x + bk.x);
            P = fast_ex2(fmaf(-0.72134752044448f, q, 0.6f * fast_lg2(t)));
            if (kk > j3) aa3 = P * fc_poly(q) * bk.y;
            accA = pack2(aa0, aa1);
            accB = pack2(aa2, aa3);
        }
        // ---- clean tiles (packed f32x2) ----
        for (int tt = t0 + 32; tt < Mpad; tt += 32) {
            const int kk = tt + lane;
            float4 uk = sU[kk]; float2 bk = sB[kk];
            const ull ukx = dup2(uk.x), uky = dup2(uk.y), ukz = dup2(uk.z);
            const ull ukw = dup2(uk.w), bkx = dup2(bk.x), bky = dup2(bk.y);
            float lo, hi;
            // pair A
            ull dotA = fma2(uxA, ukx, fma2(uyA, uky, mul2(uzA, ukz)));
            ull tA   = fma2(KN08, dotA, K1);
            ull qA   = fma2(mul2(cA, ukw), dotA, add2(sA, bkx));
            unpack2(tA, lo, hi);
            ull lgA  = pack2(fast_lg2(lo), fast_lg2(hi));
            ull zA   = fma2(K06, lgA, mul2(KNE, qA));
            unpack2(zA, lo, hi);
            ull PA   = pack2(fast_ex2(lo), fast_ex2(hi));
            ull pA   = fma2(PC5, qA, PC4);
            pA = fma2(pA, qA, PC3);
            pA = fma2(pA, qA, PC2);
            pA = fma2(pA, qA, PC1);
            pA = fma2(pA, qA, K1);
            accA = fma2(mul2(PA, pA), bky, accA);
            // pair B
            ull dotB = fma2(uxB, ukx, fma2(uyB, uky, mul2(uzB, ukz)));
            ull tB   = fma2(KN08, dotB, K1);
            ull qB   = fma2(mul2(cB, ukw), dotB, add2(sB2, bkx));
            unpack2(tB, lo, hi);
            ull lgB  = pack2(fast_lg2(lo), fast_lg2(hi));
            ull zB   = fma2(K06, lgB, mul2(KNE, qB));
            unpack2(zB, lo, hi);
            ull PB   = pack2(fast_ex2(lo), fast_ex2(hi));
            ull pB   = fma2(PC5, qB, PC4);
            pB = fma2(pB, qB, PC3);
            pB = fma2(pB, qB, PC2);
            pB = fma2(pB, qB, PC1);
            pB = fma2(pB, qB, K1);
            accB = fma2(mul2(PB, pB), bky, accB);
        }
        float a0, a1, a2, a3;
        unpack2(accA, a0, a1);
        unpack2(accB, a2, a3);
        accw = fmaf(b0.y, a0, accw);
        accw = fmaf(b1.y, a1, accw);
        accw = fmaf(b2.y, a2, accw);
        accw = fmaf(b3.y, a3, accw);
    }

    accw = warp_sum(accw);
    if (lane == 0) wr[w] = accw;

    // --- stage MLP weights (overlaps inter-warp skew before barrier) ---
    for (int t = tid; t < 1841; t += 256) {
        float v;
        if (t < 80)        v = W1[t];
        else if (t < 120)  v = B1[t - 80];
        else if (t < 1760) { int r = (t - 120) / 41, c = (t - 120) - 41 * r;
                             v = (c < 40) ? W2[r * 40 + c] : 0.f; }
        else if (t < 1800) v = B2[t - 1760];
        else if (t < 1840) v = W3[t - 1800];
        else               v = B3[0];
        sW[t] = v;
    }
    __syncthreads();

    if (tid < 8) {
        float s = wr[tid];
        #pragma unroll
        for (int d = 4; d >= 1; d >>= 1) s += __shfl_down_sync(0xffu, s, d);
        if (tid == 0) sAng = 1.3195079107728942f * s;   // 2^(1-ZETA)
    }
    __syncthreads();

    // --- fused MLP (2 -> 40 -> 40 -> 1) ---
    if (tid < 40) {
        float z = fmaf(sW[2 * tid], sAng, fmaf(sW[2 * tid + 1], sRad, sW[80 + tid]));
        sH1[tid] = __fdividef(1.f, fmaf(z, z, 1.f));
    }
    __syncthreads();
    if (tid < 40) {
        float z = sW[1760 + tid];
        const float* row = sW + 120 + tid * 41;
        #pragma unroll 8
        for (int k = 0; k < 40; k++) z = fmaf(row[k], sH1[k], z);
        sH2[tid] = __fdividef(1.f, fmaf(z, z, 1.f));
    }
    __syncthreads();
    if (w == 0) {
        float v = sW[1800 + lane] * sH2[lane];
        if (lane < 8) v = fmaf(sW[1832 + lane], sH2[32 + lane], v);
        v = warp_sum(v);
        if (lane == 0) out[i] = v + sW[1840];
    }
}

extern "C" void kernel_launch(void* const* d_in, const int* in_sizes, int n_in,
                              void* d_out, int out_size) {
    const float* x = (const float*)d_in[0];
    const int N = in_sizes[0] / 3;

    fused_kernel<<<N, 256>>>(
        x, N,
        (const float*)d_in[1],  (const float*)d_in[2],  (const float*)d_in[3],
        (const float*)d_in[4],  (const float*)d_in[5],  (const float*)d_in[6],
        (const float*)d_in[7],  (const float*)d_in[8],  (const float*)d_in[9],
        (const float*)d_in[10], (const float*)d_in[11], (const float*)d_in[12],
        (float*)d_out);
}